// round 14
// baseline (speedup 1.0000x reference)
#include <cuda_runtime.h>

// MN neuron scan: T=1000 steps, B*N = 32768 independent neurons.
//
// R12: R7's proven scalar ffma arithmetic (bit-exact, rel_err 0.0) with the
// warp-placement and scheduling fixes:
//  - 2 neurons/thread (512 warps), ops of the two neurons explicitly
//    interleaved at source so the independent chains overlap.
//  - 128-thread blocks, 128 CTAs -> 1 CTA/SM, exactly 1 warp per SMSP
//    (B300 maps SMSP = wid%4; R6/R7's 1-warp blocks stacked all warps on
//    SMSP0 -> warps contended for one scheduler).
//  - In-place reload prefetch: one LDG.64 per step, 20-step issue-to-use
//    distance; avoids front-batched load bursts (cross-CTA L1tex-queue
//    spread penalty at high MLP_p1).
// Every op is fma.rn.f32 via inline asm: a+b == fma(a,1,b), a*k == fma(a,k,-0.0)
// -> FFMA-imm (rt 1) while preserving XLA's uncontracted per-op IEEE rounding.

#define T_STEPS 1000
#define NN      512
#define BN      32768          // B * N
#define NT2     (BN / 2)       // threads, 2 neurons each = 16384
#define UPF     10             // steps per prefetch group (ping-pong x2)
#define NGRP    (T_STEPS / UPF)

__device__ __forceinline__ float ffma(float a, float b, float c) {
    float d;
    asm("fma.rn.f32 %0, %1, %2, %3;" : "=f"(d) : "f"(a), "f"(b), "f"(c));
    return d;
}

__global__ __launch_bounds__(128)
void mn_neuron_kernel(const float* __restrict__ x,
                      const float* __restrict__ lin,
                      const float* __restrict__ aarr,
                      const float* __restrict__ A1arr,
                      const float* __restrict__ A2arr,
                      float* __restrict__ out)
{
    const int gid = blockIdx.x * 128 + threadIdx.x;  // pair id in [0, NT2)
    const int n0  = (2 * gid) & (NN - 1);            // even neuron index

    // Constants (exact fp32 of the reference values)
    const float VR   = -0.07f;
    const float TR   = -0.06f;
    const float NEL  =  0.07f;   // -EL
    const float NTIN =  0.05f;   // -TINF
    const float DT   = 0.01f;
    const float K1   = 200.0f;
    const float K2   = 20.0f;
    const float Gc   = 45.24007797241211f;
    const float Bc   = 12.77495288848877f;
    const float R1   = 0.3858567178249359f;
    const float R2   = -1.1421641111373901f;
    const float NZ   = -0.0f;

    // Per-pair parameters (8B-aligned vector loads)
    const float2 l2  = *(const float2*)(lin   + n0);
    const float2 a2  = *(const float2*)(aarr  + n0);
    const float2 A12 = *(const float2*)(A1arr + n0);
    const float2 A22 = *(const float2*)(A2arr + n0);

    // State, two independent neurons (suffix a/b)
    float Va = -0.07f, i1a = 0.0f, i2a = 0.0f, Ta = -0.05f;
    float Vb = -0.07f, i1b = 0.0f, i2b = 0.0f, Tb = -0.05f;

    const float2* xp = (const float2*)x   + gid;     // stride NT2 per step
    float2*       op = (float2*)      out + gid;

    // Prime two prefetch groups (20 LDG.64 outstanding)
    float2 bufA[UPF], bufB[UPF];
#pragma unroll
    for (int u = 0; u < UPF; ++u) bufA[u] = xp[(size_t)u * NT2];
#pragma unroll
    for (int u = 0; u < UPF; ++u) bufB[u] = xp[(size_t)(UPF + u) * NT2];

    for (int g = 0; g < NGRP; g += 2) {
        const bool pfA = (g + 2) < NGRP;
        const bool pfB = (g + 3) < NGRP;
        const float2* npA = xp + (size_t)(g + 2) * UPF * NT2;
        const float2* npB = xp + (size_t)(g + 3) * UPF * NT2;

#pragma unroll
        for (int ph = 0; ph < 2; ++ph) {
#pragma unroll
            for (int u = 0; u < UPF; ++u) {
                // consume slot, immediately reload it for group g+2/g+3
                float2 xv;
                if (ph == 0) { xv = bufA[u]; if (pfA) bufA[u] = npA[(size_t)u * NT2]; }
                else         { xv = bufB[u]; if (pfB) bufB[u] = npB[(size_t)u * NT2]; }

                // ---- one step, both neurons interleaved (bit-exact order per neuron) ----
                // i1 -= (K1*i1)*DT ; i2 -= (K2*i2)*DT
                float m1a = ffma(i1a, K1, NZ);     float m1b = ffma(i1b, K1, NZ);
                float m2a = ffma(i2a, K2, NZ);     float m2b = ffma(i2b, K2, NZ);
                m1a = ffma(m1a, DT, NZ);           m1b = ffma(m1b, DT, NZ);
                m2a = ffma(m2a, DT, NZ);           m2b = ffma(m2b, DT, NZ);
                i1a = ffma(m1a, -1.0f, i1a);       i1b = ffma(m1b, -1.0f, i1b);
                i2a = ffma(m2a, -1.0f, i2a);       i2b = ffma(m2b, -1.0f, i2b);

                // V += DT * (((lin*xt + i1) + i2) - G*(V-EL))
                float lxa = ffma(l2.x, xv.x, NZ);  float lxb = ffma(l2.y, xv.y, NZ);
                float sa  = ffma(lxa, 1.0f, i1a);  float sb  = ffma(lxb, 1.0f, i1b);
                sa        = ffma(sa,  1.0f, i2a);  sb        = ffma(sb,  1.0f, i2b);
                float vea = ffma(Va, 1.0f, NEL);   float veb = ffma(Vb, 1.0f, NEL);
                float gqa = ffma(vea, Gc, NZ);     float gqb = ffma(veb, Gc, NZ);
                float dva = ffma(gqa, -1.0f, sa);  float dvb = ffma(gqb, -1.0f, sb);
                dva       = ffma(dva, DT, NZ);     dvb       = ffma(dvb, DT, NZ);
                Va        = ffma(dva, 1.0f, Va);   Vb        = ffma(dvb, 1.0f, Vb);

                // Thr += DT * (a*(V-EL) - B*(Thr-TINF))
                float v2a = ffma(Va, 1.0f, NEL);   float v2b = ffma(Vb, 1.0f, NEL);
                float t1a = ffma(a2.x, v2a, NZ);   float t1b = ffma(a2.y, v2b, NZ);
                float tta = ffma(Ta, 1.0f, NTIN);  float ttb = ffma(Tb, 1.0f, NTIN);
                float t2a = ffma(tta, Bc, NZ);     float t2b = ffma(ttb, Bc, NZ);
                float dda = ffma(t2a, -1.0f, t1a); float ddb = ffma(t2b, -1.0f, t1b);
                dda       = ffma(dda, DT, NZ);     ddb       = ffma(ddb, DT, NZ);
                Ta        = ffma(dda, 1.0f, Ta);   Tb        = ffma(ddb, 1.0f, Tb);

                // spk = (V - Thr) > 0
                float vma = ffma(Ta, -1.0f, Va);   float vmb = ffma(Tb, -1.0f, Vb);
                const bool pa = (vma > 0.0f);      const bool pb = (vmb > 0.0f);

                // reset candidates (two-rounded as reference), then exact selects
                float na1 = ffma(ffma(i1a, R1, NZ), 1.0f, A12.x);
                float nb1 = ffma(ffma(i1b, R1, NZ), 1.0f, A12.y);
                float na2 = ffma(ffma(i2a, R2, NZ), 1.0f, A22.x);
                float nb2 = ffma(ffma(i2b, R2, NZ), 1.0f, A22.y);
                i1a = pa ? na1 : i1a;              i1b = pb ? nb1 : i1b;
                i2a = pa ? na2 : i2a;              i2b = pb ? nb2 : i2b;
                Ta  = pa ? fmaxf(Ta, TR) : Ta;     Tb  = pb ? fmaxf(Tb, TR) : Tb;
                Va  = pa ? VR : Va;                Vb  = pb ? VR : Vb;

                float2 sp;
                sp.x = pa ? 1.0f : 0.0f;
                sp.y = pb ? 1.0f : 0.0f;
                op[(size_t)((g + ph) * UPF + u) * NT2] = sp;
            }
        }
    }
}

extern "C" void kernel_launch(void* const* d_in, const int* in_sizes, int n_in,
                              void* d_out, int out_size)
{
    const float* x   = (const float*)d_in[0];  // [T, B, N]
    const float* lin = (const float*)d_in[1];  // [1, N]
    const float* a   = (const float*)d_in[2];  // [1, N]
    const float* A1  = (const float*)d_in[3];  // [1, N]
    const float* A2  = (const float*)d_in[4];  // [1, N]
    float* out = (float*)d_out;                // [T, B, N]

    (void)in_sizes; (void)n_in; (void)out_size;

    mn_neuron_kernel<<<NT2 / 128, 128>>>(x, lin, a, A1, A2, out);
}